// round 2
// baseline (speedup 1.0000x reference)
#include <cuda_runtime.h>
#include <math.h>

#define T_LEN  2048
#define IN_DIM 1024
#define H_DIM  1024
#define FH     4096
#define C_DIM  1000
#define NCTA_DIR 64
#define SCAN_SMEM ((32*1024 + 1024) * 4)

// ---------------- device scratch (no allocations allowed) ----------------
__device__ __align__(16) float g_xp[2][T_LEN][FH];      // input projections (fwd, bwd-reversed order)
__device__ __align__(16) float g_hs[2][T_LEN][H_DIM];   // all hidden states (bwd stored in reversed time)
__device__ __align__(16) float g_hbuf[2][2][H_DIM];     // double-buffered h per direction
__device__ unsigned g_bar[2];                            // monotonic barrier counters per direction

__device__ __forceinline__ void bar_arrive_release(unsigned* p) {
    asm volatile("red.release.gpu.global.add.u32 [%0], %1;" :: "l"(p), "r"(1u) : "memory");
}
__device__ __forceinline__ unsigned ld_acquire_u32(const unsigned* p) {
    unsigned v;
    asm volatile("ld.acquire.gpu.global.u32 %0, [%1];" : "=r"(v) : "l"(p) : "memory");
    return v;
}

// ---------------- init: reset barrier + h0 every launch/replay ----------------
__global__ void init_kernel() {
    int tid = blockIdx.x * blockDim.x + threadIdx.x;
    if (tid < 2 * 2 * H_DIM) ((float*)g_hbuf)[tid] = 0.f;
    if (tid < 2) g_bar[tid] = 0u;
}

// ---------------- phase 1: x @ W_ih^T + b_ih + b_hh, both directions ----------------
// grid (FH/64, T/64, 2), block 256. dir==1 reads x reversed in time.
__global__ __launch_bounds__(256) void xproj_kernel(
    const float* __restrict__ x,
    const float* __restrict__ Wf, const float* __restrict__ Wb,
    const float* __restrict__ bif, const float* __restrict__ bhf,
    const float* __restrict__ bib, const float* __restrict__ bhb)
{
    const int dir = blockIdx.z;
    const float* __restrict__ W  = dir ? Wb  : Wf;
    const float* __restrict__ b1 = dir ? bib : bif;
    const float* __restrict__ b2 = dir ? bhb : bhf;

    __shared__ float sA[16][68];
    __shared__ float sB[16][68];

    const int n0 = blockIdx.x * 64;
    const int m0 = blockIdx.y * 64;
    const int tid = threadIdx.x;
    const int tx = tid & 15, ty = tid >> 4;
    const int lr = tid >> 2, lq = tid & 3;

    float acc[4][4];
    #pragma unroll
    for (int i = 0; i < 4; ++i)
        #pragma unroll
        for (int j = 0; j < 4; ++j) acc[i][j] = 0.f;

    const int s_row = m0 + lr;
    const int a_row = dir ? (T_LEN - 1 - s_row) : s_row;
    const float* aptr = x + (size_t)a_row * IN_DIM + 4*lq;
    const float* bptr = W + (size_t)(n0 + lr) * IN_DIM + 4*lq;

    for (int k0 = 0; k0 < IN_DIM; k0 += 16) {
        float4 av = *(const float4*)(aptr + k0);
        float4 bv = *(const float4*)(bptr + k0);
        sA[4*lq+0][lr] = av.x; sA[4*lq+1][lr] = av.y; sA[4*lq+2][lr] = av.z; sA[4*lq+3][lr] = av.w;
        sB[4*lq+0][lr] = bv.x; sB[4*lq+1][lr] = bv.y; sB[4*lq+2][lr] = bv.z; sB[4*lq+3][lr] = bv.w;
        __syncthreads();
        #pragma unroll
        for (int k = 0; k < 16; ++k) {
            float4 a4 = *(const float4*)&sA[k][ty*4];
            float4 b4 = *(const float4*)&sB[k][tx*4];
            float am[4] = {a4.x, a4.y, a4.z, a4.w};
            float bm[4] = {b4.x, b4.y, b4.z, b4.w};
            #pragma unroll
            for (int i = 0; i < 4; ++i)
                #pragma unroll
                for (int j = 0; j < 4; ++j)
                    acc[i][j] = fmaf(am[i], bm[j], acc[i][j]);
        }
        __syncthreads();
    }
    #pragma unroll
    for (int j = 0; j < 4; ++j) {
        int n = n0 + tx*4 + j;
        float bb = __ldg(b1 + n) + __ldg(b2 + n);
        #pragma unroll
        for (int i = 0; i < 4; ++i) {
            int t = m0 + ty*4 + i;
            g_xp[dir][t][n] = acc[i][j] + bb;
        }
    }
}

// ---------------- phase 2: persistent sequential LSTM scan ----------------
// 128 CTAs (blockIdx>>6 = direction, &63 = chunk). 256 threads = 8 warps.
// Each warp owns 2 hidden units: unit A weights (4 rows x 1024) in REGISTERS,
// unit B weights in SMEM. h broadcast via global double buffer + per-direction
// release/acquire barrier each step.
__global__ __launch_bounds__(256, 1) void scan_kernel(
    const float* __restrict__ Whh_f, const float* __restrict__ Whh_b)
{
    extern __shared__ float smem[];
    float* sW = smem;             // 32 rows x 1024 (unit-B weights)
    float* sH = smem + 32*1024;   // 1024 (staged h)

    const int dir = blockIdx.x >> 6;
    const int cb  = blockIdx.x & 63;
    const float* __restrict__ Whh = dir ? Whh_b : Whh_f;

    const int tid = threadIdx.x;
    const int w = tid >> 5;
    const int l = tid & 31;
    const int uA = cb*16 + w;        // register unit
    const int uB = cb*16 + 8 + w;    // smem unit

    // cooperative load of unit-B weights: sW row rr = lw*4+g  <->  W_hh[g*H + (cb*16+8+lw)]
    for (int i = tid; i < 32*1024/4; i += 256) {
        int rr = i >> 8;
        int col4 = i & 255;
        int lw = rr >> 2;
        int g  = rr & 3;
        int uu = cb*16 + 8 + lw;
        ((float4*)sW)[i] = __ldg((const float4*)(Whh + (size_t)(g*H_DIM + uu)*H_DIM) + col4);
    }

    // register weights for unit A: lane l holds cols {4l+128jj .. +3}, jj=0..7, per gate
    float4 wr[4][8];
    #pragma unroll
    for (int g = 0; g < 4; ++g) {
        const float4* base = (const float4*)(Whh + (size_t)(g*H_DIM + uA)*H_DIM);
        #pragma unroll
        for (int jj = 0; jj < 8; ++jj)
            wr[g][jj] = __ldg(base + (l + 32*jj));
    }
    __syncthreads();

    float cA = 0.f, cB = 0.f;            // cell state, replicated across lanes
    const float* xp = &g_xp[dir][0][0];
    float* hs = &g_hs[dir][0][0];
    const int xrow = (l & 3)*H_DIM + ((l < 4) ? uA : uB);   // rows for lanes 0..7
    unsigned* bar = &g_bar[dir];

    for (int step = 0; step < T_LEN; ++step) {
        const int cur = step & 1;
        // stage h[t] (written by other SMs last step -> bypass L1 with .cg)
        float4 hv = __ldcg((const float4*)&g_hbuf[dir][cur][0] + tid);
        ((float4*)sH)[tid] = hv;
        float xpv = (l < 8) ? __ldg(xp + (size_t)step*FH + xrow) : 0.f;
        __syncthreads();

        float acc[8];
        #pragma unroll
        for (int g = 0; g < 8; ++g) acc[g] = 0.f;

        const float4* sH4 = (const float4*)sH;
        const float4* sW4 = (const float4*)sW;
        #pragma unroll
        for (int jj = 0; jj < 8; ++jj) {
            float4 h4 = sH4[l + 32*jj];
            #pragma unroll
            for (int g = 0; g < 4; ++g) {
                float4 a = wr[g][jj];
                acc[g]   = fmaf(a.x,h4.x, fmaf(a.y,h4.y, fmaf(a.z,h4.z, fmaf(a.w,h4.w, acc[g]))));
                float4 b = sW4[(w*4 + g)*256 + l + 32*jj];
                acc[4+g] = fmaf(b.x,h4.x, fmaf(b.y,h4.y, fmaf(b.z,h4.z, fmaf(b.w,h4.w, acc[4+g]))));
            }
        }

        // butterfly reduce all 8 gate partials across the warp
        #pragma unroll
        for (int off = 16; off; off >>= 1)
            #pragma unroll
            for (int g = 0; g < 8; ++g)
                acc[g] += __shfl_xor_sync(0xffffffffu, acc[g], off);

        // lanes 0..7: select own gate sum (constant-index SEL tree), activate
        float s01 = (l & 1) ? acc[1] : acc[0];
        float s23 = (l & 1) ? acc[3] : acc[2];
        float s45 = (l & 1) ? acc[5] : acc[4];
        float s67 = (l & 1) ? acc[7] : acc[6];
        float sab = (l & 2) ? s23 : s01;
        float scd = (l & 2) ? s67 : s45;
        float pre = ((l & 4) ? scd : sab) + xpv;
        float act;
        if ((l & 3) == 2) act = tanhf(pre);
        else              act = 1.f / (1.f + expf(-pre));

        float iA = __shfl_sync(0xffffffffu, act, 0);
        float fA = __shfl_sync(0xffffffffu, act, 1);
        float gA = __shfl_sync(0xffffffffu, act, 2);
        float oA = __shfl_sync(0xffffffffu, act, 3);
        float iB = __shfl_sync(0xffffffffu, act, 4);
        float fB = __shfl_sync(0xffffffffu, act, 5);
        float gB = __shfl_sync(0xffffffffu, act, 6);
        float oB = __shfl_sync(0xffffffffu, act, 7);

        cA = fmaf(fA, cA, iA * gA);
        cB = fmaf(fB, cB, iB * gB);
        float hA = oA * tanhf(cA);
        float hB = oB * tanhf(cB);

        float* hnext = &g_hbuf[dir][cur ^ 1][0];
        if (l == 0) { hnext[uA] = hA; hs[(size_t)step*H_DIM + uA] = hA; }
        if (l == 1) { hnext[uB] = hB; hs[(size_t)step*H_DIM + uB] = hB; }
        if (l < 2) __threadfence();
        __syncthreads();
        if (tid == 0) {
            bar_arrive_release(bar);
            unsigned target = (unsigned)(step + 1) * NCTA_DIR;
            while (ld_acquire_u32(bar) < target) { }
        }
        __syncthreads();
    }
}

// ---------------- phase 3: out = concat(h_fwd, h_bwd) @ fc_W^T + fc_b ----------------
// The concat + time-reversal of the backward states is fused into the A-tile gather.
__global__ __launch_bounds__(256) void fc_kernel(
    const float* __restrict__ fcW, const float* __restrict__ fcb,
    float* __restrict__ out)
{
    __shared__ float sA[16][68];
    __shared__ float sB[16][68];
    const int n0 = blockIdx.x * 64;
    const int m0 = blockIdx.y * 64;
    const int tid = threadIdx.x;
    const int tx = tid & 15, ty = tid >> 4;
    const int lr = tid >> 2, lq = tid & 3;

    float acc[4][4];
    #pragma unroll
    for (int i = 0; i < 4; ++i)
        #pragma unroll
        for (int j = 0; j < 4; ++j) acc[i][j] = 0.f;

    const int t = m0 + lr;
    const int nrow = n0 + lr;

    for (int k0 = 0; k0 < 2*H_DIM; k0 += 16) {
        int k = k0 + 4*lq;
        const float* asrc = (k < H_DIM) ? &g_hs[0][t][k]
                                        : &g_hs[1][T_LEN - 1 - t][k - H_DIM];
        float4 av = *(const float4*)asrc;
        float4 bv = make_float4(0.f, 0.f, 0.f, 0.f);
        if (nrow < C_DIM) bv = *(const float4*)(fcW + (size_t)nrow*(2*H_DIM) + k);
        sA[4*lq+0][lr] = av.x; sA[4*lq+1][lr] = av.y; sA[4*lq+2][lr] = av.z; sA[4*lq+3][lr] = av.w;
        sB[4*lq+0][lr] = bv.x; sB[4*lq+1][lr] = bv.y; sB[4*lq+2][lr] = bv.z; sB[4*lq+3][lr] = bv.w;
        __syncthreads();
        #pragma unroll
        for (int kk = 0; kk < 16; ++kk) {
            float4 a4 = *(const float4*)&sA[kk][ty*4];
            float4 b4 = *(const float4*)&sB[kk][tx*4];
            float am[4] = {a4.x, a4.y, a4.z, a4.w};
            float bm[4] = {b4.x, b4.y, b4.z, b4.w};
            #pragma unroll
            for (int i = 0; i < 4; ++i)
                #pragma unroll
                for (int j = 0; j < 4; ++j)
                    acc[i][j] = fmaf(am[i], bm[j], acc[i][j]);
        }
        __syncthreads();
    }
    #pragma unroll
    for (int j = 0; j < 4; ++j) {
        int n = n0 + tx*4 + j;
        if (n < C_DIM) {
            float bb = __ldg(fcb + n);
            #pragma unroll
            for (int i = 0; i < 4; ++i)
                out[(size_t)(m0 + ty*4 + i)*C_DIM + n] = acc[i][j] + bb;
        }
    }
}

// ---------------- launch ----------------
extern "C" void kernel_launch(void* const* d_in, const int* in_sizes, int n_in,
                              void* d_out, int out_size)
{
    const float* x      = (const float*)d_in[0];
    const float* W_ih_f = (const float*)d_in[1];
    const float* W_hh_f = (const float*)d_in[2];
    const float* b_ih_f = (const float*)d_in[3];
    const float* b_hh_f = (const float*)d_in[4];
    const float* W_ih_b = (const float*)d_in[5];
    const float* W_hh_b = (const float*)d_in[6];
    const float* b_ih_b = (const float*)d_in[7];
    const float* b_hh_b = (const float*)d_in[8];
    const float* fc_W   = (const float*)d_in[9];
    const float* fc_b   = (const float*)d_in[10];
    float* out = (float*)d_out;

    cudaFuncSetAttribute(scan_kernel, cudaFuncAttributeMaxDynamicSharedMemorySize, SCAN_SMEM);

    init_kernel<<<16, 256>>>();
    xproj_kernel<<<dim3(FH/64, T_LEN/64, 2), 256>>>(x, W_ih_f, W_ih_b,
                                                    b_ih_f, b_hh_f, b_ih_b, b_hh_b);
    scan_kernel<<<2*NCTA_DIR, 256, SCAN_SMEM>>>(W_hh_f, W_hh_b);
    fc_kernel<<<dim3(16, T_LEN/64), 256>>>(fc_W, fc_b, out);
}

// round 3
// speedup vs baseline: 1.1424x; 1.1424x over previous
#include <cuda_runtime.h>
#include <math.h>
#include <stdint.h>

#define T_LEN  2048
#define IN_DIM 1024
#define H_DIM  1024
#define FH     4096
#define C_DIM  1000
#define NCTA_DIR 64
#define SCAN_SMEM ((32*1024 + 1024) * 4)

// ---------------- device scratch (no allocations allowed) ----------------
__device__ __align__(16) float g_xp[2][T_LEN][FH];      // input projections (fwd, bwd-reversed order)
__device__ __align__(16) float g_hs[2][T_LEN][H_DIM];   // all hidden states (bwd stored in reversed time)
__device__ __align__(16) float g_hbuf[2][2][H_DIM];     // double-buffered h per direction
__device__ unsigned g_bar[2];                            // monotonic barrier counters per direction

__device__ __forceinline__ void bar_arrive_release(unsigned* p) {
    asm volatile("red.release.gpu.global.add.u32 [%0], %1;" :: "l"(p), "r"(1u) : "memory");
}
__device__ __forceinline__ unsigned ld_acquire_u32(const unsigned* p) {
    unsigned v;
    asm volatile("ld.acquire.gpu.global.u32 %0, [%1];" : "=r"(v) : "l"(p) : "memory");
    return v;
}

__device__ __forceinline__ float to_tf32(float x) {
    uint32_t u;
    asm("cvt.rna.tf32.f32 %0, %1;" : "=r"(u) : "f"(x));
    return __uint_as_float(u);
}

__device__ __forceinline__ void mma_tf32(float* c, const uint32_t* a, const uint32_t* b) {
    asm volatile(
        "mma.sync.aligned.m16n8k8.row.col.f32.tf32.tf32.f32 "
        "{%0,%1,%2,%3}, {%4,%5,%6,%7}, {%8,%9}, {%0,%1,%2,%3};\n"
        : "+f"(c[0]), "+f"(c[1]), "+f"(c[2]), "+f"(c[3])
        : "r"(a[0]), "r"(a[1]), "r"(a[2]), "r"(a[3]), "r"(b[0]), "r"(b[1]));
}

// swizzled smem index: tile pitch 32 floats (128B), col-group XOR row
__device__ __forceinline__ int swz(int r, int c) {
    return r * 32 + ((((c >> 2) ^ (r & 7)) << 2) | (c & 3));
}

// ---------------- init: reset barrier + h0 every launch/replay ----------------
__global__ void init_kernel() {
    int tid = blockIdx.x * blockDim.x + threadIdx.x;
    if (tid < 2 * 2 * H_DIM) ((float*)g_hbuf)[tid] = 0.f;
    if (tid < 2) g_bar[tid] = 0u;
}

// ---------------- phase 1: x @ W_ih^T + b_ih + b_hh via TF32 tensor cores ----------------
// grid (FH/128, T/128, 2), block 256 (8 warps, 4x2 warp grid, 32x64 warp tile)
__global__ __launch_bounds__(256, 1) void xproj_mma(
    const float* __restrict__ x,
    const float* __restrict__ Wf, const float* __restrict__ Wb,
    const float* __restrict__ bif, const float* __restrict__ bhf,
    const float* __restrict__ bib, const float* __restrict__ bhb)
{
    const int dir = blockIdx.z;
    const float* __restrict__ W  = dir ? Wb  : Wf;
    const float* __restrict__ b1 = dir ? bib : bif;
    const float* __restrict__ b2 = dir ? bhb : bhf;

    __shared__ float sA[128 * 32];
    __shared__ float sB[128 * 32];

    const int tid = threadIdx.x;
    const int warp = tid >> 5, l = tid & 31;
    const int wm = warp >> 1, wn = warp & 1;
    const int g = l >> 2, t = l & 3;
    const int m0 = blockIdx.y * 128, n0 = blockIdx.x * 128;

    const int sr  = tid >> 3;                     // staging row 0..31
    const int sc4 = tid & 7;                      // staging col-group
    const int scs = ((sc4 ^ (sr & 7)) << 2);      // swizzled element col

    float acc[2][8][4];
    #pragma unroll
    for (int mi = 0; mi < 2; ++mi)
        #pragma unroll
        for (int ni = 0; ni < 8; ++ni)
            #pragma unroll
            for (int e = 0; e < 4; ++e) acc[mi][ni][e] = 0.f;

    float4 pa[4], pb[4];
    // prologue: load tile 0
    {
        const int kc = sc4 * 4;
        #pragma unroll
        for (int p = 0; p < 4; ++p) {
            int m = m0 + sr + 32 * p;
            int ar = dir ? (T_LEN - 1 - m) : m;
            pa[p] = *(const float4*)(x + (size_t)ar * IN_DIM + kc);
            pb[p] = *(const float4*)(W + (size_t)(n0 + sr + 32 * p) * IN_DIM + kc);
        }
        #pragma unroll
        for (int p = 0; p < 4; ++p) {
            int r = sr + 32 * p;
            float* da = &sA[r * 32 + scs];
            float* db = &sB[r * 32 + scs];
            da[0] = to_tf32(pa[p].x); da[1] = to_tf32(pa[p].y); da[2] = to_tf32(pa[p].z); da[3] = to_tf32(pa[p].w);
            db[0] = to_tf32(pb[p].x); db[1] = to_tf32(pb[p].y); db[2] = to_tf32(pb[p].z); db[3] = to_tf32(pb[p].w);
        }
    }
    __syncthreads();

    for (int kt = 0; kt < IN_DIM / 32; ++kt) {
        if (kt < IN_DIM / 32 - 1) {
            const int kc = (kt + 1) * 32 + sc4 * 4;
            #pragma unroll
            for (int p = 0; p < 4; ++p) {
                int m = m0 + sr + 32 * p;
                int ar = dir ? (T_LEN - 1 - m) : m;
                pa[p] = *(const float4*)(x + (size_t)ar * IN_DIM + kc);
                pb[p] = *(const float4*)(W + (size_t)(n0 + sr + 32 * p) * IN_DIM + kc);
            }
        }
        #pragma unroll
        for (int k8 = 0; k8 < 4; ++k8) {
            const int kk = k8 * 8;
            uint32_t a[2][4], b[8][2];
            #pragma unroll
            for (int mi = 0; mi < 2; ++mi) {
                int r = wm * 32 + mi * 16 + g;
                a[mi][0] = __float_as_uint(sA[swz(r,     kk + t)]);
                a[mi][1] = __float_as_uint(sA[swz(r + 8, kk + t)]);
                a[mi][2] = __float_as_uint(sA[swz(r,     kk + t + 4)]);
                a[mi][3] = __float_as_uint(sA[swz(r + 8, kk + t + 4)]);
            }
            #pragma unroll
            for (int ni = 0; ni < 8; ++ni) {
                int rn = wn * 64 + ni * 8 + g;
                b[ni][0] = __float_as_uint(sB[swz(rn, kk + t)]);
                b[ni][1] = __float_as_uint(sB[swz(rn, kk + t + 4)]);
            }
            #pragma unroll
            for (int mi = 0; mi < 2; ++mi)
                #pragma unroll
                for (int ni = 0; ni < 8; ++ni)
                    mma_tf32(acc[mi][ni], a[mi], b[ni]);
        }
        __syncthreads();
        if (kt < IN_DIM / 32 - 1) {
            #pragma unroll
            for (int p = 0; p < 4; ++p) {
                int r = sr + 32 * p;
                float* da = &sA[r * 32 + scs];
                float* db = &sB[r * 32 + scs];
                da[0] = to_tf32(pa[p].x); da[1] = to_tf32(pa[p].y); da[2] = to_tf32(pa[p].z); da[3] = to_tf32(pa[p].w);
                db[0] = to_tf32(pb[p].x); db[1] = to_tf32(pb[p].y); db[2] = to_tf32(pb[p].z); db[3] = to_tf32(pb[p].w);
            }
            __syncthreads();
        }
    }

    // epilogue: add bias, store
    #pragma unroll
    for (int mi = 0; mi < 2; ++mi) {
        int r0 = m0 + wm * 32 + mi * 16 + g;
        #pragma unroll
        for (int ni = 0; ni < 8; ++ni) {
            int n = n0 + wn * 64 + ni * 8 + 2 * t;
            float bb0 = __ldg(b1 + n)     + __ldg(b2 + n);
            float bb1 = __ldg(b1 + n + 1) + __ldg(b2 + n + 1);
            float2 v0 = make_float2(acc[mi][ni][0] + bb0, acc[mi][ni][1] + bb1);
            float2 v1 = make_float2(acc[mi][ni][2] + bb0, acc[mi][ni][3] + bb1);
            *(float2*)&g_xp[dir][r0][n]     = v0;
            *(float2*)&g_xp[dir][r0 + 8][n] = v1;
        }
    }
}

// ---------------- phase 2: persistent sequential LSTM scan (unchanged, known-good) ----------------
__global__ __launch_bounds__(256, 1) void scan_kernel(
    const float* __restrict__ Whh_f, const float* __restrict__ Whh_b)
{
    extern __shared__ float smem[];
    float* sW = smem;             // 32 rows x 1024 (unit-B weights)
    float* sH = smem + 32*1024;   // 1024 (staged h)

    const int dir = blockIdx.x >> 6;
    const int cb  = blockIdx.x & 63;
    const float* __restrict__ Whh = dir ? Whh_b : Whh_f;

    const int tid = threadIdx.x;
    const int w = tid >> 5;
    const int l = tid & 31;
    const int uA = cb*16 + w;        // register unit
    const int uB = cb*16 + 8 + w;    // smem unit

    for (int i = tid; i < 32*1024/4; i += 256) {
        int rr = i >> 8;
        int col4 = i & 255;
        int lw = rr >> 2;
        int g  = rr & 3;
        int uu = cb*16 + 8 + lw;
        ((float4*)sW)[i] = __ldg((const float4*)(Whh + (size_t)(g*H_DIM + uu)*H_DIM) + col4);
    }

    float4 wr[4][8];
    #pragma unroll
    for (int g = 0; g < 4; ++g) {
        const float4* base = (const float4*)(Whh + (size_t)(g*H_DIM + uA)*H_DIM);
        #pragma unroll
        for (int jj = 0; jj < 8; ++jj)
            wr[g][jj] = __ldg(base + (l + 32*jj));
    }
    __syncthreads();

    float cA = 0.f, cB = 0.f;
    const float* xp = &g_xp[dir][0][0];
    float* hs = &g_hs[dir][0][0];
    const int xrow = (l & 3)*H_DIM + ((l < 4) ? uA : uB);
    unsigned* bar = &g_bar[dir];

    for (int step = 0; step < T_LEN; ++step) {
        const int cur = step & 1;
        float4 hv = __ldcg((const float4*)&g_hbuf[dir][cur][0] + tid);
        ((float4*)sH)[tid] = hv;
        float xpv = (l < 8) ? __ldg(xp + (size_t)step*FH + xrow) : 0.f;
        __syncthreads();

        float acc[8];
        #pragma unroll
        for (int g = 0; g < 8; ++g) acc[g] = 0.f;

        const float4* sH4 = (const float4*)sH;
        const float4* sW4 = (const float4*)sW;
        #pragma unroll
        for (int jj = 0; jj < 8; ++jj) {
            float4 h4 = sH4[l + 32*jj];
            #pragma unroll
            for (int g = 0; g < 4; ++g) {
                float4 a = wr[g][jj];
                acc[g]   = fmaf(a.x,h4.x, fmaf(a.y,h4.y, fmaf(a.z,h4.z, fmaf(a.w,h4.w, acc[g]))));
                float4 b = sW4[(w*4 + g)*256 + l + 32*jj];
                acc[4+g] = fmaf(b.x,h4.x, fmaf(b.y,h4.y, fmaf(b.z,h4.z, fmaf(b.w,h4.w, acc[4+g]))));
            }
        }

        #pragma unroll
        for (int off = 16; off; off >>= 1)
            #pragma unroll
            for (int g = 0; g < 8; ++g)
                acc[g] += __shfl_xor_sync(0xffffffffu, acc[g], off);

        float s01 = (l & 1) ? acc[1] : acc[0];
        float s23 = (l & 1) ? acc[3] : acc[2];
        float s45 = (l & 1) ? acc[5] : acc[4];
        float s67 = (l & 1) ? acc[7] : acc[6];
        float sab = (l & 2) ? s23 : s01;
        float scd = (l & 2) ? s67 : s45;
        float pre = ((l & 4) ? scd : sab) + xpv;
        float act;
        if ((l & 3) == 2) act = tanhf(pre);
        else              act = 1.f / (1.f + expf(-pre));

        float iA = __shfl_sync(0xffffffffu, act, 0);
        float fA = __shfl_sync(0xffffffffu, act, 1);
        float gA = __shfl_sync(0xffffffffu, act, 2);
        float oA = __shfl_sync(0xffffffffu, act, 3);
        float iB = __shfl_sync(0xffffffffu, act, 4);
        float fB = __shfl_sync(0xffffffffu, act, 5);
        float gB = __shfl_sync(0xffffffffu, act, 6);
        float oB = __shfl_sync(0xffffffffu, act, 7);

        cA = fmaf(fA, cA, iA * gA);
        cB = fmaf(fB, cB, iB * gB);
        float hA = oA * tanhf(cA);
        float hB = oB * tanhf(cB);

        float* hnext = &g_hbuf[dir][cur ^ 1][0];
        if (l == 0) { hnext[uA] = hA; hs[(size_t)step*H_DIM + uA] = hA; }
        if (l == 1) { hnext[uB] = hB; hs[(size_t)step*H_DIM + uB] = hB; }
        if (l < 2) __threadfence();
        __syncthreads();
        if (tid == 0) {
            bar_arrive_release(bar);
            unsigned target = (unsigned)(step + 1) * NCTA_DIR;
            while (ld_acquire_u32(bar) < target) { }
        }
        __syncthreads();
    }
}

// ---------------- phase 3: out = concat(h_fwd, h_bwd) @ fc_W^T + fc_b via TF32 MMA ----------------
// grid (1024/128=8, T/128=16), block 256. concat + time-reverse fused into A gather.
__global__ __launch_bounds__(256, 1) void fc_mma(
    const float* __restrict__ fcW, const float* __restrict__ fcb,
    float* __restrict__ out)
{
    __shared__ float sA[128 * 32];
    __shared__ float sB[128 * 32];

    const int tid = threadIdx.x;
    const int warp = tid >> 5, l = tid & 31;
    const int wm = warp >> 1, wn = warp & 1;
    const int g = l >> 2, t = l & 3;
    const int m0 = blockIdx.y * 128, n0 = blockIdx.x * 128;

    const int sr  = tid >> 3;
    const int sc4 = tid & 7;
    const int scs = ((sc4 ^ (sr & 7)) << 2);

    float acc[2][8][4];
    #pragma unroll
    for (int mi = 0; mi < 2; ++mi)
        #pragma unroll
        for (int ni = 0; ni < 8; ++ni)
            #pragma unroll
            for (int e = 0; e < 4; ++e) acc[mi][ni][e] = 0.f;

    float4 pa[4], pb[4];
    {
        const int kc = sc4 * 4;
        #pragma unroll
        for (int p = 0; p < 4; ++p) {
            int m = m0 + sr + 32 * p;
            const float* asrc = (kc < H_DIM) ? &g_hs[0][m][kc]
                                             : &g_hs[1][T_LEN - 1 - m][kc - H_DIM];
            pa[p] = *(const float4*)asrc;
            int n = n0 + sr + 32 * p;
            pb[p] = (n < C_DIM) ? *(const float4*)(fcW + (size_t)n * (2 * H_DIM) + kc)
                                : make_float4(0.f, 0.f, 0.f, 0.f);
        }
        #pragma unroll
        for (int p = 0; p < 4; ++p) {
            int r = sr + 32 * p;
            float* da = &sA[r * 32 + scs];
            float* db = &sB[r * 32 + scs];
            da[0] = to_tf32(pa[p].x); da[1] = to_tf32(pa[p].y); da[2] = to_tf32(pa[p].z); da[3] = to_tf32(pa[p].w);
            db[0] = to_tf32(pb[p].x); db[1] = to_tf32(pb[p].y); db[2] = to_tf32(pb[p].z); db[3] = to_tf32(pb[p].w);
        }
    }
    __syncthreads();

    const int KTOT = 2 * H_DIM;
    for (int kt = 0; kt < KTOT / 32; ++kt) {
        if (kt < KTOT / 32 - 1) {
            const int kc = (kt + 1) * 32 + sc4 * 4;
            #pragma unroll
            for (int p = 0; p < 4; ++p) {
                int m = m0 + sr + 32 * p;
                const float* asrc = (kc < H_DIM) ? &g_hs[0][m][kc]
                                                 : &g_hs[1][T_LEN - 1 - m][kc - H_DIM];
                pa[p] = *(const float4*)asrc;
                int n = n0 + sr + 32 * p;
                pb[p] = (n < C_DIM) ? *(const float4*)(fcW + (size_t)n * (2 * H_DIM) + kc)
                                    : make_float4(0.f, 0.f, 0.f, 0.f);
            }
        }
        #pragma unroll
        for (int k8 = 0; k8 < 4; ++k8) {
            const int kk = k8 * 8;
            uint32_t a[2][4], b[8][2];
            #pragma unroll
            for (int mi = 0; mi < 2; ++mi) {
                int r = wm * 32 + mi * 16 + g;
                a[mi][0] = __float_as_uint(sA[swz(r,     kk + t)]);
                a[mi][1] = __float_as_uint(sA[swz(r + 8, kk + t)]);
                a[mi][2] = __float_as_uint(sA[swz(r,     kk + t + 4)]);
                a[mi][3] = __float_as_uint(sA[swz(r + 8, kk + t + 4)]);
            }
            #pragma unroll
            for (int ni = 0; ni < 8; ++ni) {
                int rn = wn * 64 + ni * 8 + g;
                b[ni][0] = __float_as_uint(sB[swz(rn, kk + t)]);
                b[ni][1] = __float_as_uint(sB[swz(rn, kk + t + 4)]);
            }
            #pragma unroll
            for (int mi = 0; mi < 2; ++mi)
                #pragma unroll
                for (int ni = 0; ni < 8; ++ni)
                    mma_tf32(acc[mi][ni], a[mi], b[ni]);
        }
        __syncthreads();
        if (kt < KTOT / 32 - 1) {
            #pragma unroll
            for (int p = 0; p < 4; ++p) {
                int r = sr + 32 * p;
                float* da = &sA[r * 32 + scs];
                float* db = &sB[r * 32 + scs];
                da[0] = to_tf32(pa[p].x); da[1] = to_tf32(pa[p].y); da[2] = to_tf32(pa[p].z); da[3] = to_tf32(pa[p].w);
                db[0] = to_tf32(pb[p].x); db[1] = to_tf32(pb[p].y); db[2] = to_tf32(pb[p].z); db[3] = to_tf32(pb[p].w);
            }
            __syncthreads();
        }
    }

    #pragma unroll
    for (int mi = 0; mi < 2; ++mi) {
        int r0 = m0 + wm * 32 + mi * 16 + g;
        #pragma unroll
        for (int ni = 0; ni < 8; ++ni) {
            int n = n0 + wn * 64 + ni * 8 + 2 * t;
            if (n < C_DIM) {   // n even, C_DIM even -> pair fully in-bounds
                float bb0 = __ldg(fcb + n);
                float bb1 = __ldg(fcb + n + 1);
                float2 v0 = make_float2(acc[mi][ni][0] + bb0, acc[mi][ni][1] + bb1);
                float2 v1 = make_float2(acc[mi][ni][2] + bb0, acc[mi][ni][3] + bb1);
                *(float2*)&out[(size_t)r0 * C_DIM + n]       = v0;
                *(float2*)&out[(size_t)(r0 + 8) * C_DIM + n] = v1;
            }
        }
    }
}

// ---------------- launch ----------------
extern "C" void kernel_launch(void* const* d_in, const int* in_sizes, int n_in,
                              void* d_out, int out_size)
{
    const float* x      = (const float*)d_in[0];
    const float* W_ih_f = (const float*)d_in[1];
    const float* W_hh_f = (const float*)d_in[2];
    const float* b_ih_f = (const float*)d_in[3];
    const float* b_hh_f = (const float*)d_in[4];
    const float* W_ih_b = (const float*)d_in[5];
    const float* W_hh_b = (const float*)d_in[6];
    const float* b_ih_b = (const float*)d_in[7];
    const float* b_hh_b = (const float*)d_in[8];
    const float* fc_W   = (const float*)d_in[9];
    const float* fc_b   = (const float*)d_in[10];
    float* out = (float*)d_out;

    cudaFuncSetAttribute(scan_kernel, cudaFuncAttributeMaxDynamicSharedMemorySize, SCAN_SMEM);

    init_kernel<<<16, 256>>>();
    xproj_mma<<<dim3(FH/128, T_LEN/128, 2), 256>>>(x, W_ih_f, W_ih_b,
                                                   b_ih_f, b_hh_f, b_ih_b, b_hh_b);
    scan_kernel<<<2*NCTA_DIR, 256, SCAN_SMEM>>>(W_hh_f, W_hh_b);
    fc_mma<<<dim3(8, T_LEN/128), 256>>>(fc_W, fc_b, out);
}